// round 13
// baseline (speedup 1.0000x reference)
#include <cuda_runtime.h>
#include <math.h>
#include <stdint.h>

#define NUM_ITEMS  10000
#define NUM_USERS  10000
#define NUM_GROUPS 5000
#define EMB_DIM    64
#define BATCH      16384
#define NCOLS      10000

#define WCAP   512            // k1 per-warp hit-index buffer (>= max hits per 2KB block)
#define BLKF4  128            // float4 per cp.async stream block (2 KB)
#define GCAP   320            // CSR capacity per gu row (mean ~100, 20+ sigma margin)

// Scratch (allocation-free rule: __device__ globals)
__device__ float    g_user_embeds[NUM_USERS * EMB_DIM];    // divided (clamped cnt)
__device__ float    g_group_embeds[NUM_GROUPS * EMB_DIM];  // divided (raw cnt)
__device__ uint16_t g_gcsr[NUM_GROUPS * GCAP];             // gu hit indices
__device__ int      g_gcnt[NUM_GROUPS];                    // gu hit counts

// ---- cp.async helpers -----------------------------------------------------
__device__ __forceinline__ void cp_async16(void* smem, const void* gmem) {
    unsigned saddr = (unsigned)__cvta_generic_to_shared(smem);
    asm volatile("cp.async.cg.shared.global [%0], [%1], 16;"
                 :: "r"(saddr), "l"(gmem));
}
#define CP_COMMIT()  asm volatile("cp.async.commit_group;" ::: "memory")
#define CP_WAIT(n)   asm volatile("cp.async.wait_group %0;" :: "n"(n) : "memory")

// ---- byte-pack detection: entries are exactly {0.0f,1.0f}; byte3==0x3F iff 1
__device__ __forceinline__ unsigned detect4(float4 v) {
    const unsigned p = __byte_perm(__float_as_uint(v.x), __float_as_uint(v.y), 0x0073) |
                       __byte_perm(__float_as_uint(v.z), __float_as_uint(v.w), 0x7300);
    return p & 0x01010101u;
}

// ---------------------------------------------------------------------------
// Batched gather from smem idx list (k1 role): 8 indep LDG.64 in flight.
// ---------------------------------------------------------------------------
__device__ __forceinline__ void load_batch(const int* __restrict__ idxbuf, int j,
                                           int lane, const float2* __restrict__ emb2,
                                           float2* e)
{
    int id[8];
    #pragma unroll
    for (int t = 0; t < 8; ++t) id[t] = idxbuf[j + t];
    #pragma unroll
    for (int t = 0; t < 8; ++t) e[t] = emb2[id[t] * 32 + lane];
}

__device__ __forceinline__ void gather_accumulate(const int* __restrict__ idxbuf,
                                                  int nh, int lane,
                                                  const float2* __restrict__ emb2,
                                                  float2& acc)
{
    const int nfull = nh & ~7;
    if (nfull) {
        float2 ea[8];
        load_batch(idxbuf, 0, lane, emb2, ea);
        for (int j = 8; j < nfull; j += 8) {
            float2 eb[8];
            load_batch(idxbuf, j, lane, emb2, eb);
            #pragma unroll
            for (int t = 0; t < 8; ++t) { acc.x += ea[t].x; acc.y += ea[t].y; }
            #pragma unroll
            for (int t = 0; t < 8; ++t) ea[t] = eb[t];
        }
        #pragma unroll
        for (int t = 0; t < 8; ++t) { acc.x += ea[t].x; acc.y += ea[t].y; }
    }
    for (int j = nfull; j < nh; ++j) {
        const float2 e = emb2[idxbuf[j] * 32 + lane];
        acc.x += e.x; acc.y += e.y;
    }
}

// ---------------------------------------------------------------------------
// FUSED kernel: 3750 blocks, round-robin roles so both populations co-reside.
//   role k1  (2 of 3): ui row scan via cp.async stage + smem idx buffer +
//                      deferred batched gather of item_emb -> user_embeds.
//   role scan(1 of 3): gu row pure stream (reg-prefetch MLP=8, __ldcs) ->
//                      uint16 CSR hit list + count (soaks DRAM headroom).
// ---------------------------------------------------------------------------
__global__ __launch_bounds__(128, 9)
void fused_kernel(const float* __restrict__ ui,
                  const float* __restrict__ gu,
                  const float* __restrict__ item_emb)
{
    __shared__ float4 s_stage[4][2][BLKF4];       // 16 KB (k1 role)
    __shared__ int    s_idx[4][WCAP];             // 8 KB  (k1 role)
    __shared__ int    s_nh[4];

    const int lane = threadIdx.x & 31;
    const int wl   = threadIdx.x >> 5;
    const int b    = blockIdx.x;
    const int r    = b % 3;
    const int q    = b / 3;                       // 0..1249

    if (lane == 0) s_nh[wl] = 0;
    __syncwarp();

    if (r == 2) {
        // ================= scan role: gu row -> CSR =================
        const int row = q * 4 + wl;               // 0..4999
        const float4* __restrict__ row4 = (const float4*)(gu + (size_t)row * NCOLS);
        const int ncols4 = NCOLS / 4;             // 2500
        uint16_t* __restrict__ csr = g_gcsr + (size_t)row * GCAP;

        for (int base = 0; base < ncols4; base += 256) {
            float4 v[8];
            #pragma unroll
            for (int u = 0; u < 8; ++u) {
                const int jj = base + u * 32 + lane;
                v[u] = (jj < ncols4) ? __ldcs(&row4[jj])
                                     : make_float4(0.f, 0.f, 0.f, 0.f);
            }
            unsigned br[8];
            unsigned ucnt = 0u;
            #pragma unroll
            for (int u = 0; u < 8; ++u) {
                br[u] = detect4(v[u]);
                ucnt = __dp4a(br[u], 0x01010101u, ucnt);
            }
            int off = atomicAdd(&s_nh[wl], (int)ucnt);
            const int ebase = base * 4 + lane * 4;
            #pragma unroll
            for (int u = 0; u < 8; ++u) {
                unsigned bm = br[u];
                while (bm) {
                    const int k = __ffs(bm) - 1;
                    bm &= bm - 1;
                    if (off < GCAP)
                        csr[off] = (uint16_t)(ebase + u * 128 + (k >> 3));
                    ++off;
                }
            }
        }
        __syncwarp();
        if (lane == 0) g_gcnt[row] = s_nh[wl];
        return;
    }

    // ================= k1 role: ui row -> user_embeds =================
    const int row = (q * 2 + r) * 4 + wl;         // 0..9999
    const int ncols4 = NCOLS / 4;
    const int nblk   = (ncols4 + BLKF4 - 1) / BLKF4;
    const float4* __restrict__ row4 = (const float4*)(ui + (size_t)row * NCOLS);
    const float2* __restrict__ emb2 = (const float2*)item_emb;
    int* idxbuf = s_idx[wl];

    float2 acc = make_float2(0.f, 0.f);
    int nh = 0, tot = 0;

    {   // prologue: stage block 0
        #pragma unroll
        for (int u = 0; u < 4; ++u) {
            const int jj = u * 32 + lane;
            if (jj < ncols4) cp_async16(&s_stage[wl][0][u * 32 + lane], &row4[jj]);
        }
        CP_COMMIT();
    }

    for (int bb = 0; bb < nblk; ++bb) {
        if (bb + 1 < nblk) {
            const int nb = (bb + 1) * BLKF4;
            #pragma unroll
            for (int u = 0; u < 4; ++u) {
                const int jj = nb + u * 32 + lane;
                if (jj < ncols4)
                    cp_async16(&s_stage[wl][(bb + 1) & 1][u * 32 + lane], &row4[jj]);
            }
        }
        CP_COMMIT();
        CP_WAIT(1);

        const int base = bb * BLKF4;
        const float4* stage = s_stage[wl][bb & 1];
        unsigned br[4];
        unsigned ucnt = 0u;
        #pragma unroll
        for (int u = 0; u < 4; ++u) {
            const int jj = base + u * 32 + lane;
            float4 v = (jj < ncols4) ? stage[u * 32 + lane]
                                     : make_float4(0.f, 0.f, 0.f, 0.f);
            br[u] = detect4(v);
            ucnt = __dp4a(br[u], 0x01010101u, ucnt);
        }
        const int cnt  = (int)ucnt;
        const int btot = __reduce_add_sync(0xffffffffu, cnt);
        if (nh + btot > WCAP) {
            __syncwarp();
            gather_accumulate(idxbuf, nh, lane, emb2, acc);
            tot += nh; nh = 0;
            if (lane == 0) s_nh[wl] = 0;
            __syncwarp();
        }
        int off = atomicAdd(&s_nh[wl], cnt);
        const int ebase = base * 4 + lane * 4;
        #pragma unroll
        for (int u = 0; u < 4; ++u) {
            unsigned bm = br[u];
            while (bm) {
                const int k = __ffs(bm) - 1;
                bm &= bm - 1;
                idxbuf[off++] = ebase + u * 128 + (k >> 3);
            }
        }
        nh += btot;
        __syncwarp();
    }
    CP_WAIT(0);

    gather_accumulate(idxbuf, nh, lane, emb2, acc);
    tot += nh;

    const float inv = 1.0f / fmaxf((float)tot, 1.0f);   // clamped divisor (k1)
    float2* __restrict__ out2 = (float2*)(g_user_embeds + (size_t)row * EMB_DIM);
    out2[lane] = make_float2(acc.x * inv, acc.y * inv);
}

// ---------------------------------------------------------------------------
// Group gather: one warp per group; HALF-WARP FLOAT4 PAIRED gather — one
// warp-instruction fetches TWO 256B user_embeds rows (32 lanes x 16B).
// Batches of 16 indices, double-buffered. Raw-count divisor (>=1 guaranteed).
// Slow path rescans gu if CSR overflowed (statistically never).
// ---------------------------------------------------------------------------
__global__ __launch_bounds__(128)
void group_gather_kernel(const float* __restrict__ gu)
{
    const int lane = threadIdx.x & 31;
    const int wl   = threadIdx.x >> 5;
    const int row  = blockIdx.x * 4 + wl;
    if (row >= NUM_GROUPS) return;

    const int h  = lane >> 4;                     // half-warp id
    const int li = lane & 15;                     // lane within half

    const float4* __restrict__ ue4 = (const float4*)g_user_embeds;
    const int cnt = g_gcnt[row];
    float4 acc = make_float4(0.f, 0.f, 0.f, 0.f);

    if (cnt <= GCAP) {
        const uint16_t* __restrict__ csr = g_gcsr + (size_t)row * GCAP;
        float4 ea[8];
        const int nfull = cnt & ~15;              // multiples of 16 indices
        if (nfull) {
            #pragma unroll
            for (int t = 0; t < 8; ++t)
                ea[t] = ue4[(int)csr[2 * t + h] * 16 + li];
            for (int j = 16; j < nfull; j += 16) {
                float4 eb[8];
                #pragma unroll
                for (int t = 0; t < 8; ++t)
                    eb[t] = ue4[(int)csr[j + 2 * t + h] * 16 + li];
                #pragma unroll
                for (int t = 0; t < 8; ++t) {
                    acc.x += ea[t].x; acc.y += ea[t].y;
                    acc.z += ea[t].z; acc.w += ea[t].w;
                }
                #pragma unroll
                for (int t = 0; t < 8; ++t) ea[t] = eb[t];
            }
            #pragma unroll
            for (int t = 0; t < 8; ++t) {
                acc.x += ea[t].x; acc.y += ea[t].y;
                acc.z += ea[t].z; acc.w += ea[t].w;
            }
        }
        // tail: pairs (each half takes one index per step)
        for (int j = nfull; j < cnt; j += 2) {
            const int jj = j + h;
            if (jj < cnt) {
                const float4 e = ue4[(int)csr[jj] * 16 + li];
                acc.x += e.x; acc.y += e.y; acc.z += e.z; acc.w += e.w;
            }
        }
    } else {
        // slow path: rescan the gu row inline (never expected)
        const float2* __restrict__ ue2 = (const float2*)g_user_embeds;
        float2 a2 = make_float2(0.f, 0.f);
        const float4* __restrict__ row4 = (const float4*)(gu + (size_t)row * NCOLS);
        for (int base = 0; base < NCOLS / 4; base += 32) {
            const int j4 = base + lane;
            float4 v = (j4 < NCOLS / 4) ? row4[j4] : make_float4(0.f, 0.f, 0.f, 0.f);
            #pragma unroll
            for (int c = 0; c < 4; ++c) {
                unsigned m = __ballot_sync(0xffffffffu, (&v.x)[c] > 0.f);
                while (m) {
                    const int l = __ffs(m) - 1;
                    m &= m - 1;
                    const float2 e = ue2[((base + l) * 4 + c) * 32 + lane];
                    a2.x += e.x; a2.y += e.y;
                }
            }
        }
        const float inv = 1.0f / (float)cnt;
        float2* __restrict__ o2 = (float2*)(g_group_embeds + (size_t)row * EMB_DIM);
        o2[lane] = make_float2(a2.x * inv, a2.y * inv);
        return;
    }

    // combine halves, normalize, write (lanes 0-15 cover the 256B row)
    acc.x += __shfl_xor_sync(0xffffffffu, acc.x, 16);
    acc.y += __shfl_xor_sync(0xffffffffu, acc.y, 16);
    acc.z += __shfl_xor_sync(0xffffffffu, acc.z, 16);
    acc.w += __shfl_xor_sync(0xffffffffu, acc.w, 16);

    const float inv = 1.0f / (float)cnt;          // raw divisor, no clamp
    if (h == 0) {
        float4* __restrict__ out4 = (float4*)(g_group_embeds + (size_t)row * EMB_DIM);
        out4[li] = make_float4(acc.x * inv, acc.y * inv, acc.z * inv, acc.w * inv);
    }
}

// ---------------------------------------------------------------------------
// MLP, 4 threads per batch element (32 concat-dims each), shfl-reduced.
// ---------------------------------------------------------------------------
__global__ __launch_bounds__(256)
void mlp_kernel(const float* __restrict__ item_emb,
                const float* __restrict__ W1,  // [128, 8]
                const float* __restrict__ b1,  // [8]
                const float* __restrict__ W2,  // [8, 1]
                const float* __restrict__ b2,  // [1]
                const int*   __restrict__ gidx,
                const int*   __restrict__ iidx,
                float* __restrict__ out)
{
    __shared__ float sW1[2 * EMB_DIM * 8];
    __shared__ float sb1[8];
    __shared__ float sW2[8];
    __shared__ float sb2;

    for (int i = threadIdx.x; i < 2 * EMB_DIM * 8; i += blockDim.x)
        sW1[i] = W1[i];
    if (threadIdx.x < 8) {
        sb1[threadIdx.x] = b1[threadIdx.x];
        sW2[threadIdx.x] = W2[threadIdx.x];
    }
    if (threadIdx.x == 0) sb2 = b2[0];
    __syncthreads();

    const int gtid = blockIdx.x * 256 + threadIdx.x;
    const int elem = gtid >> 2;
    const int qq   = gtid & 3;                    // which 32-dim slice
    if (elem >= BATCH) return;

    const int d0 = qq * 32;                       // concat dims [d0, d0+32)
    const float* src = (qq < 2)
        ? (g_group_embeds + (size_t)gidx[elem] * EMB_DIM + d0)
        : (item_emb       + (size_t)iidx[elem] * EMB_DIM + (d0 - EMB_DIM));

    float h[8];
    #pragma unroll
    for (int k = 0; k < 8; ++k) h[k] = (qq == 0) ? sb1[k] : 0.f;

    const float4* __restrict__ s4 = (const float4*)src;
    #pragma unroll
    for (int j = 0; j < 8; ++j) {                 // 8 x float4 = 32 dims
        const float4 e = s4[j];
        const int dd = d0 + 4 * j;
        #pragma unroll
        for (int k = 0; k < 8; ++k) {
            h[k] += e.x * sW1[(dd    ) * 8 + k];
            h[k] += e.y * sW1[(dd + 1) * 8 + k];
            h[k] += e.z * sW1[(dd + 2) * 8 + k];
            h[k] += e.w * sW1[(dd + 3) * 8 + k];
        }
    }

    // reduce h across the element's 4 threads (lanes differ in bits 0,1)
    #pragma unroll
    for (int k = 0; k < 8; ++k) {
        h[k] += __shfl_xor_sync(0xffffffffu, h[k], 1);
        h[k] += __shfl_xor_sync(0xffffffffu, h[k], 2);
    }

    if (qq == 0) {
        float y = sb2;
        #pragma unroll
        for (int k = 0; k < 8; ++k)
            y += fmaxf(h[k], 0.0f) * sW2[k];
        out[elem] = 1.0f / (1.0f + expf(-y));
    }
}

// ---------------------------------------------------------------------------
extern "C" void kernel_launch(void* const* d_in, const int* in_sizes, int n_in,
                              void* d_out, int out_size)
{
    const float* item_emb = (const float*)d_in[0];
    const float* ui       = (const float*)d_in[1];
    const float* gu       = (const float*)d_in[2];
    const float* W1       = (const float*)d_in[3];
    const float* b1       = (const float*)d_in[4];
    const float* W2       = (const float*)d_in[5];
    const float* b2       = (const float*)d_in[6];
    const int*   gidx     = (const int*)d_in[7];
    const int*   iidx     = (const int*)d_in[8];
    float* out            = (float*)d_out;

    // 1) fused: k1 (ui scan+gather -> user_embeds) || gu scan -> CSR
    fused_kernel<<<3750, 128>>>(ui, gu, item_emb);

    // 2) group gather from CSR (user_embeds L2-resident, paired float4)
    group_gather_kernel<<<1250, 128>>>(gu);

    // 3) MLP head (x4 thread parallelism)
    mlp_kernel<<<(BATCH * 4) / 256, 256>>>(item_emb, W1, b1, W2, b2,
                                           gidx, iidx, out);
}

// round 14
// speedup vs baseline: 1.0087x; 1.0087x over previous
#include <cuda_runtime.h>
#include <math.h>
#include <stdint.h>

#define NUM_ITEMS  10000
#define NUM_USERS  10000
#define NUM_GROUPS 5000
#define EMB_DIM    64
#define BATCH      16384
#define NCOLS      10000

#define WCAP   512            // k1 per-warp hit-index buffer (>= max hits per 2KB block)
#define BLKF4  128            // float4 per cp.async stream block (2 KB)
#define GCAP   320            // CSR capacity per gu row (mean ~100, 20+ sigma margin)

// Scratch (allocation-free rule: __device__ globals)
__device__ float    g_user_embeds[NUM_USERS * EMB_DIM];    // divided (clamped cnt)
__device__ float    g_group_embeds[NUM_GROUPS * EMB_DIM];  // divided (raw cnt)
__device__ uint16_t g_gcsr[NUM_GROUPS * GCAP];             // gu hit indices
__device__ int      g_gcnt[NUM_GROUPS];                    // gu hit counts

// ---- cp.async helpers -----------------------------------------------------
__device__ __forceinline__ void cp_async16(void* smem, const void* gmem) {
    unsigned saddr = (unsigned)__cvta_generic_to_shared(smem);
    asm volatile("cp.async.cg.shared.global [%0], [%1], 16;"
                 :: "r"(saddr), "l"(gmem));
}
#define CP_COMMIT()  asm volatile("cp.async.commit_group;" ::: "memory")
#define CP_WAIT(n)   asm volatile("cp.async.wait_group %0;" :: "n"(n) : "memory")

// ---- byte-pack detection: entries are exactly {0.0f,1.0f}; byte3==0x3F iff 1
__device__ __forceinline__ unsigned detect4(float4 v) {
    const unsigned p = __byte_perm(__float_as_uint(v.x), __float_as_uint(v.y), 0x0073) |
                       __byte_perm(__float_as_uint(v.z), __float_as_uint(v.w), 0x7300);
    return p & 0x01010101u;
}

// ---------------------------------------------------------------------------
// Batched gather from int idx list in smem (k1 role): 8 indep LDG.64 in
// flight, double-buffered so one L2 latency is exposed per flush.
// ---------------------------------------------------------------------------
__device__ __forceinline__ void load_batch(const int* __restrict__ idxbuf, int j,
                                           int lane, const float2* __restrict__ emb2,
                                           float2* e)
{
    int id[8];
    #pragma unroll
    for (int t = 0; t < 8; ++t) id[t] = idxbuf[j + t];
    #pragma unroll
    for (int t = 0; t < 8; ++t) e[t] = emb2[id[t] * 32 + lane];
}

__device__ __forceinline__ void gather_accumulate(const int* __restrict__ idxbuf,
                                                  int nh, int lane,
                                                  const float2* __restrict__ emb2,
                                                  float2& acc)
{
    const int nfull = nh & ~7;
    if (nfull) {
        float2 ea[8];
        load_batch(idxbuf, 0, lane, emb2, ea);
        for (int j = 8; j < nfull; j += 8) {
            float2 eb[8];
            load_batch(idxbuf, j, lane, emb2, eb);
            #pragma unroll
            for (int t = 0; t < 8; ++t) { acc.x += ea[t].x; acc.y += ea[t].y; }
            #pragma unroll
            for (int t = 0; t < 8; ++t) ea[t] = eb[t];
        }
        #pragma unroll
        for (int t = 0; t < 8; ++t) { acc.x += ea[t].x; acc.y += ea[t].y; }
    }
    for (int j = nfull; j < nh; ++j) {
        const float2 e = emb2[idxbuf[j] * 32 + lane];
        acc.x += e.x; acc.y += e.y;
    }
}

// ---------------------------------------------------------------------------
// FUSED kernel (unchanged from R12/R13 best): 3750 blocks, round-robin roles.
//   role k1  (2 of 3): ui row scan via cp.async stage + smem idx buffer +
//                      deferred batched gather of item_emb -> user_embeds.
//   role scan(1 of 3): gu row pure stream -> uint16 CSR hit list + count.
// ---------------------------------------------------------------------------
__global__ __launch_bounds__(128, 9)
void fused_kernel(const float* __restrict__ ui,
                  const float* __restrict__ gu,
                  const float* __restrict__ item_emb)
{
    __shared__ float4 s_stage[4][2][BLKF4];       // 16 KB (k1 role)
    __shared__ int    s_idx[4][WCAP];             // 8 KB  (k1 role)
    __shared__ int    s_nh[4];

    const int lane = threadIdx.x & 31;
    const int wl   = threadIdx.x >> 5;
    const int b    = blockIdx.x;
    const int r    = b % 3;
    const int q    = b / 3;                       // 0..1249

    if (lane == 0) s_nh[wl] = 0;
    __syncwarp();

    if (r == 2) {
        // ================= scan role: gu row -> CSR =================
        const int row = q * 4 + wl;               // 0..4999
        const float4* __restrict__ row4 = (const float4*)(gu + (size_t)row * NCOLS);
        const int ncols4 = NCOLS / 4;             // 2500
        uint16_t* __restrict__ csr = g_gcsr + (size_t)row * GCAP;

        for (int base = 0; base < ncols4; base += 256) {
            float4 v[8];
            #pragma unroll
            for (int u = 0; u < 8; ++u) {
                const int jj = base + u * 32 + lane;
                v[u] = (jj < ncols4) ? __ldcs(&row4[jj])
                                     : make_float4(0.f, 0.f, 0.f, 0.f);
            }
            unsigned br[8];
            unsigned ucnt = 0u;
            #pragma unroll
            for (int u = 0; u < 8; ++u) {
                br[u] = detect4(v[u]);
                ucnt = __dp4a(br[u], 0x01010101u, ucnt);
            }
            int off = atomicAdd(&s_nh[wl], (int)ucnt);
            const int ebase = base * 4 + lane * 4;
            #pragma unroll
            for (int u = 0; u < 8; ++u) {
                unsigned bm = br[u];
                while (bm) {
                    const int k = __ffs(bm) - 1;
                    bm &= bm - 1;
                    if (off < GCAP)
                        csr[off] = (uint16_t)(ebase + u * 128 + (k >> 3));
                    ++off;
                }
            }
        }
        __syncwarp();
        if (lane == 0) g_gcnt[row] = s_nh[wl];
        return;
    }

    // ================= k1 role: ui row -> user_embeds =================
    const int row = (q * 2 + r) * 4 + wl;         // 0..9999
    const int ncols4 = NCOLS / 4;
    const int nblk   = (ncols4 + BLKF4 - 1) / BLKF4;
    const float4* __restrict__ row4 = (const float4*)(ui + (size_t)row * NCOLS);
    const float2* __restrict__ emb2 = (const float2*)item_emb;
    int* idxbuf = s_idx[wl];

    float2 acc = make_float2(0.f, 0.f);
    int nh = 0, tot = 0;

    {   // prologue: stage block 0
        #pragma unroll
        for (int u = 0; u < 4; ++u) {
            const int jj = u * 32 + lane;
            if (jj < ncols4) cp_async16(&s_stage[wl][0][u * 32 + lane], &row4[jj]);
        }
        CP_COMMIT();
    }

    for (int bb = 0; bb < nblk; ++bb) {
        if (bb + 1 < nblk) {
            const int nb = (bb + 1) * BLKF4;
            #pragma unroll
            for (int u = 0; u < 4; ++u) {
                const int jj = nb + u * 32 + lane;
                if (jj < ncols4)
                    cp_async16(&s_stage[wl][(bb + 1) & 1][u * 32 + lane], &row4[jj]);
            }
        }
        CP_COMMIT();
        CP_WAIT(1);

        const int base = bb * BLKF4;
        const float4* stage = s_stage[wl][bb & 1];
        unsigned br[4];
        unsigned ucnt = 0u;
        #pragma unroll
        for (int u = 0; u < 4; ++u) {
            const int jj = base + u * 32 + lane;
            float4 v = (jj < ncols4) ? stage[u * 32 + lane]
                                     : make_float4(0.f, 0.f, 0.f, 0.f);
            br[u] = detect4(v);
            ucnt = __dp4a(br[u], 0x01010101u, ucnt);
        }
        const int cnt  = (int)ucnt;
        const int btot = __reduce_add_sync(0xffffffffu, cnt);
        if (nh + btot > WCAP) {
            __syncwarp();
            gather_accumulate(idxbuf, nh, lane, emb2, acc);
            tot += nh; nh = 0;
            if (lane == 0) s_nh[wl] = 0;
            __syncwarp();
        }
        int off = atomicAdd(&s_nh[wl], cnt);
        const int ebase = base * 4 + lane * 4;
        #pragma unroll
        for (int u = 0; u < 4; ++u) {
            unsigned bm = br[u];
            while (bm) {
                const int k = __ffs(bm) - 1;
                bm &= bm - 1;
                idxbuf[off++] = ebase + u * 128 + (k >> 3);
            }
        }
        nh += btot;
        __syncwarp();
    }
    CP_WAIT(0);

    gather_accumulate(idxbuf, nh, lane, emb2, acc);
    tot += nh;

    const float inv = 1.0f / fmaxf((float)tot, 1.0f);   // clamped divisor (k1)
    float2* __restrict__ out2 = (float2*)(g_user_embeds + (size_t)row * EMB_DIM);
    out2[lane] = make_float2(acc.x * inv, acc.y * inv);
}

// ---------------------------------------------------------------------------
// Group gather, SPLIT: warp pair per group. Warp half handles a contiguous
// slice of the CSR list (chain length halved); partials combined via smem.
// R12's float2 batched/double-buffered gather form (proven). Raw-count
// divisor (>=1 guaranteed). Slow path rescans gu if CSR overflowed.
// ---------------------------------------------------------------------------
__global__ __launch_bounds__(256)
void group_gather_kernel(const float* __restrict__ gu)
{
    __shared__ float2 s_part[4][32];              // even-warp partials per pair

    const int lane = threadIdx.x & 31;
    const int wl   = threadIdx.x >> 5;            // 0..7
    const int pair = wl >> 1;                     // 0..3
    const int half = wl & 1;
    const int row  = blockIdx.x * 4 + pair;       // 1250 blocks -> 5000 groups

    const float2* __restrict__ ue2 = (const float2*)g_user_embeds;
    const int cnt = g_gcnt[row];
    float2 acc = make_float2(0.f, 0.f);
    bool fast = (cnt <= GCAP);

    if (fast) {
        const uint16_t* __restrict__ csr16 = g_gcsr + (size_t)row * GCAP;
        // contiguous split: half0 = [0, c0), half1 = [c0, cnt)
        const int c0 = (cnt / 2 + 7) & ~7;        // multiple of 8
        const int jb = half ? min(c0, cnt) : 0;
        const int je = half ? cnt : min(c0, cnt);
        const int n  = je - jb;

        const int nfull = n & ~7;
        if (nfull) {
            float2 ea[8];
            int id[8];
            #pragma unroll
            for (int t = 0; t < 8; ++t) id[t] = csr16[jb + t];
            #pragma unroll
            for (int t = 0; t < 8; ++t) ea[t] = ue2[id[t] * 32 + lane];
            for (int j = 8; j < nfull; j += 8) {
                float2 eb[8];
                #pragma unroll
                for (int t = 0; t < 8; ++t) id[t] = csr16[jb + j + t];
                #pragma unroll
                for (int t = 0; t < 8; ++t) eb[t] = ue2[id[t] * 32 + lane];
                #pragma unroll
                for (int t = 0; t < 8; ++t) { acc.x += ea[t].x; acc.y += ea[t].y; }
                #pragma unroll
                for (int t = 0; t < 8; ++t) ea[t] = eb[t];
            }
            #pragma unroll
            for (int t = 0; t < 8; ++t) { acc.x += ea[t].x; acc.y += ea[t].y; }
        }
        for (int j = jb + nfull; j < je; ++j) {
            const float2 e = ue2[(int)csr16[j] * 32 + lane];
            acc.x += e.x; acc.y += e.y;
        }
    } else if (half == 0) {
        // slow path: rescan the gu row inline (never expected); half 0 only
        const float4* __restrict__ row4 = (const float4*)(gu + (size_t)row * NCOLS);
        for (int base = 0; base < NCOLS / 4; base += 32) {
            const int j4 = base + lane;
            float4 v = (j4 < NCOLS / 4) ? row4[j4] : make_float4(0.f, 0.f, 0.f, 0.f);
            #pragma unroll
            for (int c = 0; c < 4; ++c) {
                unsigned m = __ballot_sync(0xffffffffu, (&v.x)[c] > 0.f);
                while (m) {
                    const int l = __ffs(m) - 1;
                    m &= m - 1;
                    const float2 e = ue2[((base + l) * 4 + c) * 32 + lane];
                    acc.x += e.x; acc.y += e.y;
                }
            }
        }
    }

    // combine pair: even warp deposits, odd warp finalizes
    if (half == 0) s_part[pair][lane] = acc;
    __syncthreads();
    if (half == 1) {
        const float2 o = s_part[pair][lane];
        acc.x += o.x; acc.y += o.y;
        const float inv = 1.0f / (float)cnt;      // raw divisor, no clamp
        float2* __restrict__ out2 =
            (float2*)(g_group_embeds + (size_t)row * EMB_DIM);
        out2[lane] = make_float2(acc.x * inv, acc.y * inv);
    }
}

// ---------------------------------------------------------------------------
// MLP, 4 threads per batch element (32 concat-dims each), shfl-reduced.
// ---------------------------------------------------------------------------
__global__ __launch_bounds__(256)
void mlp_kernel(const float* __restrict__ item_emb,
                const float* __restrict__ W1,  // [128, 8]
                const float* __restrict__ b1,  // [8]
                const float* __restrict__ W2,  // [8, 1]
                const float* __restrict__ b2,  // [1]
                const int*   __restrict__ gidx,
                const int*   __restrict__ iidx,
                float* __restrict__ out)
{
    __shared__ float sW1[2 * EMB_DIM * 8];
    __shared__ float sb1[8];
    __shared__ float sW2[8];
    __shared__ float sb2;

    for (int i = threadIdx.x; i < 2 * EMB_DIM * 8; i += blockDim.x)
        sW1[i] = W1[i];
    if (threadIdx.x < 8) {
        sb1[threadIdx.x] = b1[threadIdx.x];
        sW2[threadIdx.x] = W2[threadIdx.x];
    }
    if (threadIdx.x == 0) sb2 = b2[0];
    __syncthreads();

    const int gtid = blockIdx.x * 256 + threadIdx.x;
    const int elem = gtid >> 2;
    const int qq   = gtid & 3;                    // which 32-dim slice
    if (elem >= BATCH) return;

    const int d0 = qq * 32;                       // concat dims [d0, d0+32)
    const float* src = (qq < 2)
        ? (g_group_embeds + (size_t)gidx[elem] * EMB_DIM + d0)
        : (item_emb       + (size_t)iidx[elem] * EMB_DIM + (d0 - EMB_DIM));

    float h[8];
    #pragma unroll
    for (int k = 0; k < 8; ++k) h[k] = (qq == 0) ? sb1[k] : 0.f;

    const float4* __restrict__ s4 = (const float4*)src;
    #pragma unroll
    for (int j = 0; j < 8; ++j) {                 // 8 x float4 = 32 dims
        const float4 e = s4[j];
        const int dd = d0 + 4 * j;
        #pragma unroll
        for (int k = 0; k < 8; ++k) {
            h[k] += e.x * sW1[(dd    ) * 8 + k];
            h[k] += e.y * sW1[(dd + 1) * 8 + k];
            h[k] += e.z * sW1[(dd + 2) * 8 + k];
            h[k] += e.w * sW1[(dd + 3) * 8 + k];
        }
    }

    // reduce h across the element's 4 threads (lanes differ in bits 0,1)
    #pragma unroll
    for (int k = 0; k < 8; ++k) {
        h[k] += __shfl_xor_sync(0xffffffffu, h[k], 1);
        h[k] += __shfl_xor_sync(0xffffffffu, h[k], 2);
    }

    if (qq == 0) {
        float y = sb2;
        #pragma unroll
        for (int k = 0; k < 8; ++k)
            y += fmaxf(h[k], 0.0f) * sW2[k];
        out[elem] = 1.0f / (1.0f + expf(-y));
    }
}

// ---------------------------------------------------------------------------
extern "C" void kernel_launch(void* const* d_in, const int* in_sizes, int n_in,
                              void* d_out, int out_size)
{
    const float* item_emb = (const float*)d_in[0];
    const float* ui       = (const float*)d_in[1];
    const float* gu       = (const float*)d_in[2];
    const float* W1       = (const float*)d_in[3];
    const float* b1       = (const float*)d_in[4];
    const float* W2       = (const float*)d_in[5];
    const float* b2       = (const float*)d_in[6];
    const int*   gidx     = (const int*)d_in[7];
    const int*   iidx     = (const int*)d_in[8];
    float* out            = (float*)d_out;

    // 1) fused: k1 (ui scan+gather -> user_embeds) || gu scan -> CSR
    fused_kernel<<<3750, 128>>>(ui, gu, item_emb);

    // 2) group gather from CSR (split warp-pairs; user_embeds L2-resident)
    group_gather_kernel<<<1250, 256>>>(gu);

    // 3) MLP head (x4 thread parallelism)
    mlp_kernel<<<(BATCH * 4) / 256, 256>>>(item_emb, W1, b1, W2, b2,
                                           gidx, iidx, out);
}